// round 2
// baseline (speedup 1.0000x reference)
#include <cuda_runtime.h>
#include <cstdint>

#define BN  2
#define NP  4096
#define KN  32
#define TOK 128
#define CQ  (BN*NP)
#define RAD2 (0.16f*0.16f)

// Scratch (no allocations allowed)
__device__ float    g_F1 [CQ*TOK];   // feature @ W1[0:64]
__device__ float    g_A1b[CQ*TOK];   // abs_pe @ W1[91:187] + b1
__device__ int      g_idx[CQ*KN];
__device__ unsigned g_gmax[BN*TOK];

__device__ __forceinline__ unsigned f2ord(float f){
    unsigned u = __float_as_uint(f);
    return (u & 0x80000000u) ? ~u : (u | 0x80000000u);
}
__device__ __forceinline__ float ord2f(unsigned u){
    return __uint_as_float((u & 0x80000000u) ? (u ^ 0x80000000u) : ~u);
}

__global__ void init_gmax_kernel(){
    int t = blockIdx.x*blockDim.x + threadIdx.x;
    if (t < BN*TOK) g_gmax[t] = 0u;   // encodes -inf-ish (most negative)
}

// ---------------------------------------------------------------------------
// Per-point precompute: F1[row][c], A1b[row][c]
// ---------------------------------------------------------------------------
__global__ void precompute_kernel(const float* __restrict__ xyz,
                                  const float* __restrict__ feat,
                                  const float* __restrict__ W1,
                                  const float* __restrict__ b1){
    int row = blockIdx.x;          // 0..8191
    int c   = threadIdx.x;         // 0..127
    __shared__ float sf[64], spe[96], sx[3];
    if (c < 3)  sx[c] = xyz[row*3 + c];
    if (c < 64) sf[c] = feat[row*64 + c];
    __syncthreads();
    if (c < 96){
        int a = c >> 5, t = c & 31, kk = t & 15;
        // freqs = exp(-ln(10000)/15 * k)
        float f = __expf(-0.6140226914886731f * (float)kk);
        float ang = sx[a] * f;
        spe[c] = (t < 16) ? __sinf(ang) : __cosf(ang);
    }
    __syncthreads();
    float accF = 0.f;
    float accA = b1[c];
    #pragma unroll 16
    for (int d = 0; d < 64; d++) accF += sf[d]  * W1[d*TOK + c];
    #pragma unroll 16
    for (int d = 0; d < 96; d++) accA += spe[d] * W1[(91+d)*TOK + c];
    g_F1 [row*TOK + c] = accF;
    g_A1b[row*TOK + c] = accA;
}

// ---------------------------------------------------------------------------
// Ball query: first KN ascending indices with d2 <= r^2 (fill with first)
// ---------------------------------------------------------------------------
__global__ void neighbor_kernel(const float* __restrict__ xyz){
    int gtid = blockIdx.x*blockDim.x + threadIdx.x;
    int w    = gtid >> 5;          // query id
    int lane = threadIdx.x & 31;
    if (w >= CQ) return;
    int b = w >> 12, i = w & (NP-1);
    const float* xb = xyz + (size_t)b*NP*3;
    float cx = xb[i*3], cy = xb[i*3+1], cz = xb[i*3+2];
    __shared__ int s_idx[8][KN];
    int wl = threadIdx.x >> 5;
    int count = 0;
    for (int base = 0; base < NP && count < KN; base += 32){
        int j = base + lane;
        float dx = xb[j*3]   - cx;
        float dy = xb[j*3+1] - cy;
        float dz = xb[j*3+2] - cz;
        float d2 = dx*dx + dy*dy + dz*dz;
        bool hit = (d2 <= RAD2);
        unsigned m = __ballot_sync(0xFFFFFFFFu, hit);
        int pos = count + __popc(m & ((1u << lane) - 1u));
        if (hit && pos < KN) s_idx[wl][pos] = j;
        count += __popc(m);
    }
    __syncwarp();
    int stored = count < KN ? count : KN;
    int first  = s_idx[wl][0];     // count >= 1 always (self)
    int v = (lane < stored) ? s_idx[wl][lane] : first;
    g_idx[(size_t)w*KN + lane] = v;
}

// ---------------------------------------------------------------------------
// Main fused kernel: layer1 (27-dim pair part + precomputed) -> relu ->
// layer2 GEMM (smem W2, 4x4 register tiles) -> max over K -> global atomicMax
// Persistent blocks: W2 / W1rel loaded into smem once per block.
// ---------------------------------------------------------------------------
__global__ __launch_bounds__(256, 2)
void main_kernel(const float* __restrict__ xyz,
                 const float* __restrict__ W1,
                 const float* __restrict__ W2){
    extern __shared__ float smem[];
    float*    W2s   = smem;                         // 128*128
    float*    h1s   = W2s   + TOK*TOK;              // 32*128
    float*    W1rel = h1s   + KN*TOK;               // 27*128
    float*    pes   = W1rel + 27*TOK;               // 32*28
    int*      sj    = (int*)(pes + KN*28);          // 32
    unsigned* encs  = (unsigned*)(sj + KN);         // 128

    const int tid = threadIdx.x;
    for (int t = tid; t < TOK*TOK; t += 256) W2s[t]   = W2[t];
    for (int t = tid; t < 27*TOK;  t += 256) W1rel[t] = W1[64*TOK + t];

    const int c  = tid & 127, k2 = tid >> 7;   // phase A mapping
    const int ct = tid & 31,  kt = tid >> 5;   // phase B mapping

    // rel-pe freqs: exp(-ln(10000)/3 * k)
    const float fr0 = 1.0f, fr1 = 0.046415888336127795f,
                fr2 = 0.0021544346900318843f, fr3 = 1.0e-4f;

    for (int q = blockIdx.x; q < CQ; q += gridDim.x){
        int b = q >> 12, i = q & (NP-1);
        const float* xb = xyz + (size_t)b*NP*3;
        __syncthreads();  // prev iter done with smem; first iter: W2s/W1rel ready

        if (tid < KN){
            int k = tid;
            int j = g_idx[(size_t)q*KN + k];
            sj[k] = j;
            float rx = xb[j*3]   - xb[i*3];
            float ry = xb[j*3+1] - xb[i*3+1];
            float rz = xb[j*3+2] - xb[i*3+2];
            float* p = pes + k*28;
            p[0] = rx; p[1] = ry; p[2] = rz;
            float r3v[3] = {rx, ry, rz};
            #pragma unroll
            for (int a = 0; a < 3; a++){
                float x = r3v[a];
                float s0,c0,s1,c1,s2,c2,s3,c3;
                __sincosf(x*fr0, &s0, &c0);
                __sincosf(x*fr1, &s1, &c1);
                __sincosf(x*fr2, &s2, &c2);
                __sincosf(x*fr3, &s3, &c3);
                float* pa = p + 3 + a*8;
                pa[0]=s0; pa[1]=s1; pa[2]=s2; pa[3]=s3;
                pa[4]=c0; pa[5]=c1; pa[6]=c2; pa[7]=c3;
            }
        }
        __syncthreads();

        // Phase A: h1[k][c] = relu(A1b[i][c] + F1[j][c] + pe27 . W1rel[:,c])
        {
            float a1 = g_A1b[(size_t)q*TOK + c];
            #pragma unroll
            for (int kk = 0; kk < 16; kk++){
                int k = (kk << 1) | k2;
                int j = sj[k];
                float acc = a1 + g_F1[((size_t)b*NP + j)*TOK + c];
                const float* p = pes + k*28;
                #pragma unroll
                for (int d = 0; d < 27; d++)
                    acc += p[d] * W1rel[d*TOK + c];
                h1s[k*TOK + c] = fmaxf(acc, 0.f);
            }
        }
        if (tid < TOK) encs[tid] = 0u;
        __syncthreads();

        // Phase B: h2 = h1 @ W2 ; per-thread 4 rows x 4 cols
        {
            float acc[4][4];
            #pragma unroll
            for (int r = 0; r < 4; r++)
                #pragma unroll
                for (int cc = 0; cc < 4; cc++) acc[r][cc] = 0.f;

            const int kr = kt*4, c4 = ct*4;
            #pragma unroll 8
            for (int d = 0; d < TOK; d += 4){
                float4 A0 = *(const float4*)(h1s + (kr+0)*TOK + d);
                float4 A1 = *(const float4*)(h1s + (kr+1)*TOK + d);
                float4 A2 = *(const float4*)(h1s + (kr+2)*TOK + d);
                float4 A3 = *(const float4*)(h1s + (kr+3)*TOK + d);
                float4 B0 = *(const float4*)(W2s + (d+0)*TOK + c4);
                float4 B1 = *(const float4*)(W2s + (d+1)*TOK + c4);
                float4 B2 = *(const float4*)(W2s + (d+2)*TOK + c4);
                float4 B3 = *(const float4*)(W2s + (d+3)*TOK + c4);
                #define STEP(r, A) \
                    acc[r][0] += A.x*B0.x + A.y*B1.x + A.z*B2.x + A.w*B3.x; \
                    acc[r][1] += A.x*B0.y + A.y*B1.y + A.z*B2.y + A.w*B3.y; \
                    acc[r][2] += A.x*B0.z + A.y*B1.z + A.z*B2.z + A.w*B3.z; \
                    acc[r][3] += A.x*B0.w + A.y*B1.w + A.z*B2.w + A.w*B3.w;
                STEP(0, A0) STEP(1, A1) STEP(2, A2) STEP(3, A3)
                #undef STEP
            }
            #pragma unroll
            for (int cc = 0; cc < 4; cc++){
                float m = fmaxf(fmaxf(acc[0][cc], acc[1][cc]),
                                fmaxf(acc[2][cc], acc[3][cc]));
                atomicMax(&encs[c4 + cc], f2ord(m));
            }
        }
        __syncthreads();
        if (tid < TOK) atomicMax(&g_gmax[b*TOK + tid], encs[tid]);
    }
}

// ---------------------------------------------------------------------------
// Final: g = max + b2 ; g = relu(g@W3+b3) ; out = g@W4+b4
// ---------------------------------------------------------------------------
__global__ void final_kernel(const float* __restrict__ b2,
                             const float* __restrict__ W3,
                             const float* __restrict__ b3,
                             const float* __restrict__ W4,
                             const float* __restrict__ b4,
                             float* __restrict__ out){
    int b = blockIdx.x, c = threadIdx.x;
    __shared__ float g[TOK], h[TOK];
    g[c] = ord2f(g_gmax[b*TOK + c]) + b2[c];
    __syncthreads();
    float acc = b3[c];
    #pragma unroll 16
    for (int d = 0; d < TOK; d++) acc += g[d] * W3[d*TOK + c];
    h[c] = fmaxf(acc, 0.f);
    __syncthreads();
    float acc2 = b4[c];
    #pragma unroll 16
    for (int d = 0; d < TOK; d++) acc2 += h[d] * W4[d*TOK + c];
    out[b*TOK + c] = acc2;
}

// ---------------------------------------------------------------------------
extern "C" void kernel_launch(void* const* d_in, const int* in_sizes, int n_in,
                              void* d_out, int out_size){
    const float* xyz  = (const float*)d_in[0];
    const float* feat = (const float*)d_in[1];
    const float* W1   = (const float*)d_in[2];
    const float* b1   = (const float*)d_in[3];
    const float* W2   = (const float*)d_in[4];
    const float* b2   = (const float*)d_in[5];
    const float* W3   = (const float*)d_in[6];
    const float* b3   = (const float*)d_in[7];
    const float* W4   = (const float*)d_in[8];
    const float* b4   = (const float*)d_in[9];
    float* out = (float*)d_out;

    const int MAIN_SMEM = (TOK*TOK + KN*TOK + 27*TOK + KN*28)*4 + KN*4 + TOK*4;
    cudaFuncSetAttribute(main_kernel,
                         cudaFuncAttributeMaxDynamicSharedMemorySize, MAIN_SMEM);

    init_gmax_kernel<<<1, 256>>>();
    precompute_kernel<<<CQ, 128>>>(xyz, feat, W1, b1);
    neighbor_kernel<<<CQ/8, 256>>>(xyz);
    main_kernel<<<296, 256, MAIN_SMEM>>>(xyz, W1, W2);
    final_kernel<<<BN, TOK>>>(b2, W3, b3, W4, b4, out);
}

// round 3
// speedup vs baseline: 2.1294x; 2.1294x over previous
#include <cuda_runtime.h>
#include <cstdint>

#define BN  2
#define NP  4096
#define KN  32
#define TOK 128
#define CQ  (BN*NP)
#define RAD2 (0.16f*0.16f)
#define H1S 144   // h1 smem row stride (uint), conflict-free LDS.128
#define PESS 48   // pes smem row stride

// Scratch (no allocations allowed)
__device__ float    g_F1 [CQ*TOK];   // feature @ W1[0:64]
__device__ float    g_A1b[CQ*TOK];   // abs_pe @ W1[91:187] + b1
__device__ int      g_idx[CQ*KN];
__device__ unsigned g_gmax[BN*TOK];

__device__ __forceinline__ unsigned f2ord(float f){
    unsigned u = __float_as_uint(f);
    return (u & 0x80000000u) ? ~u : (u | 0x80000000u);
}
__device__ __forceinline__ float ord2f(unsigned u){
    return __uint_as_float((u & 0x80000000u) ? (u ^ 0x80000000u) : ~u);
}
__device__ __forceinline__ unsigned tf32c(float f){
    unsigned u; asm("cvt.rna.tf32.f32 %0, %1;" : "=r"(u) : "f"(f)); return u;
}
// permuted column index: within each 16-col group, order so that an A-frag's
// {tig, tig+4} cols of two adjacent k8-tiles are 4 consecutive words
__device__ __host__ __forceinline__ int pcol(int c){
    int t = (c >> 3) & 1;
    int pos = 2*(c & 3) + ((c >> 2) & 1);
    return (c & ~15) + pos*2 + t;
}
__device__ __forceinline__ void mma8(float* c, unsigned a0, unsigned a1,
                                     unsigned a2, unsigned a3,
                                     unsigned b0, unsigned b1){
    asm volatile("mma.sync.aligned.m16n8k8.row.col.f32.tf32.tf32.f32 "
        "{%0,%1,%2,%3},{%4,%5,%6,%7},{%8,%9},{%0,%1,%2,%3};"
        : "+f"(c[0]), "+f"(c[1]), "+f"(c[2]), "+f"(c[3])
        : "r"(a0), "r"(a1), "r"(a2), "r"(a3), "r"(b0), "r"(b1));
}

// ---------------------------------------------------------------------------
// Per-point precompute: F1[row][c], A1b[row][c]  (+ g_gmax init in block 0)
// ---------------------------------------------------------------------------
__global__ void precompute_kernel(const float* __restrict__ xyz,
                                  const float* __restrict__ feat,
                                  const float* __restrict__ W1,
                                  const float* __restrict__ b1){
    int row = blockIdx.x;          // 0..8191
    int c   = threadIdx.x;         // 0..127
    if (blockIdx.x == 0){ g_gmax[c] = 0u; g_gmax[128+c] = 0u; }
    __shared__ float sf[64], spe[96], sx[3];
    if (c < 3)  sx[c] = xyz[row*3 + c];
    if (c < 64) sf[c] = feat[row*64 + c];
    __syncthreads();
    if (c < 96){
        int a = c >> 5, t = c & 31, kk = t & 15;
        float f = __expf(-0.6140226914886731f * (float)kk);
        float ang = sx[a] * f;
        spe[c] = (t < 16) ? __sinf(ang) : __cosf(ang);
    }
    __syncthreads();
    float accF = 0.f;
    float accA = b1[c];
    #pragma unroll 16
    for (int d = 0; d < 64; d++) accF += sf[d]  * W1[d*TOK + c];
    #pragma unroll 16
    for (int d = 0; d < 96; d++) accA += spe[d] * W1[(91+d)*TOK + c];
    g_F1 [row*TOK + c] = accF;
    g_A1b[row*TOK + c] = accA;
}

// ---------------------------------------------------------------------------
// Ball query: first KN ascending indices with d2 <= r^2 (fill with first)
// ---------------------------------------------------------------------------
__global__ void neighbor_kernel(const float* __restrict__ xyz){
    int gtid = blockIdx.x*blockDim.x + threadIdx.x;
    int w    = gtid >> 5;
    int lane = threadIdx.x & 31;
    if (w >= CQ) return;
    int b = w >> 12, i = w & (NP-1);
    const float* xb = xyz + (size_t)b*NP*3;
    float cx = xb[i*3], cy = xb[i*3+1], cz = xb[i*3+2];
    __shared__ int s_idx[8][KN];
    int wl = threadIdx.x >> 5;
    int count = 0;
    for (int base = 0; base < NP && count < KN; base += 32){
        int j = base + lane;
        float dx = xb[j*3]   - cx;
        float dy = xb[j*3+1] - cy;
        float dz = xb[j*3+2] - cz;
        float d2 = dx*dx + dy*dy + dz*dz;
        bool hit = (d2 <= RAD2);
        unsigned m = __ballot_sync(0xFFFFFFFFu, hit);
        int pos = count + __popc(m & ((1u << lane) - 1u));
        if (hit && pos < KN) s_idx[wl][pos] = j;
        count += __popc(m);
    }
    __syncwarp();
    int stored = count < KN ? count : KN;
    int first  = s_idx[wl][0];
    int v = (lane < stored) ? s_idx[wl][lane] : first;
    g_idx[(size_t)w*KN + lane] = v;
}

// ---------------------------------------------------------------------------
// Main kernel: 4 queries per iteration (128 rows), both layers via tf32 mma.
// W2/W1rel B-fragments held in registers; h1 staged in smem (permuted layout).
// ---------------------------------------------------------------------------
__global__ __launch_bounds__(256, 1)
void main_kernel(const float* __restrict__ xyz,
                 const float* __restrict__ W1,
                 const float* __restrict__ W2){
    extern __shared__ unsigned char smraw[];
    unsigned* h1s  = (unsigned*)smraw;               // 128*144
    unsigned* pes  = h1s + 128*H1S;                  // 128*48
    float*    sA1b = (float*)(pes + 128*PESS);       // 4*128
    int*      sj   = (int*)(sA1b + 4*TOK);           // 4*32
    unsigned* sbmax= (unsigned*)(sj + 4*KN);         // 2*128

    const int tid  = threadIdx.x;
    const int w    = tid >> 5;
    const int lane = tid & 31;
    const int g    = lane >> 2;
    const int tig  = lane & 3;
    const int n0   = w * 16;

    sbmax[tid] = 0u;

    // B-fragments for W2 (16 k-tiles x 2 n-tiles) and W1rel (4 k-tiles, K pad 32)
    unsigned bw2[16][2][2];
    #pragma unroll
    for (int kt = 0; kt < 16; kt++)
        #pragma unroll
        for (int nt = 0; nt < 2; nt++){
            int col = n0 + nt*8 + g;
            bw2[kt][nt][0] = tf32c(W2[(kt*8 + tig    )*TOK + col]);
            bw2[kt][nt][1] = tf32c(W2[(kt*8 + tig + 4)*TOK + col]);
        }
    unsigned bw1[4][2][2];
    #pragma unroll
    for (int kt = 0; kt < 4; kt++)
        #pragma unroll
        for (int nt = 0; nt < 2; nt++){
            int col = n0 + nt*8 + g;
            int k0 = kt*8 + tig, k1 = k0 + 4;
            bw1[kt][nt][0] = (k0 < 27) ? tf32c(W1[(64+k0)*TOK + col]) : 0u;
            bw1[kt][nt][1] = (k1 < 27) ? tf32c(W1[(64+k1)*TOK + col]) : 0u;
        }
    // h1 store positions (constant per lane)
    int pc[2][2];
    #pragma unroll
    for (int nt = 0; nt < 2; nt++){
        int c0 = n0 + nt*8 + 2*tig;
        pc[nt][0] = pcol(c0); pc[nt][1] = pcol(c0+1);
    }

    for (int it = blockIdx.x; it < CQ/4; it += gridDim.x){
        int q0 = it * 4;
        int b  = q0 >> 12;
        const float* xb = xyz + (size_t)b*NP*3;
        const float* f1b = g_F1 + (size_t)b*NP*TOK;
        __syncthreads();   // h1s (prev phase B) + pes/sA1b free

        // ---- stage: sj, pes (tf32, permuted), sA1b ----
        if (tid < 128){
            int r = tid, qq = r >> 5, k = r & 31;
            int q = q0 + qq, i = q & (NP-1);
            int j = g_idx[q*KN + k];
            sj[qq*KN + k] = j;
            float ix = xb[i*3], iy = xb[i*3+1], iz = xb[i*3+2];
            float rx = xb[j*3]-ix, ry = xb[j*3+1]-iy, rz = xb[j*3+2]-iz;
            unsigned* pr = pes + r*PESS;
            pr[pcol(0)] = tf32c(rx);
            pr[pcol(1)] = tf32c(ry);
            pr[pcol(2)] = tf32c(rz);
            float rv[3] = {rx, ry, rz};
            const float fr[4] = {1.0f, 0.046415888336127795f,
                                 0.0021544346900318843f, 1.0e-4f};
            #pragma unroll
            for (int a = 0; a < 3; a++)
                #pragma unroll
                for (int f = 0; f < 4; f++){
                    float s, c2;
                    __sincosf(rv[a]*fr[f], &s, &c2);
                    pr[pcol(3 + a*8 + f)]     = tf32c(s);
                    pr[pcol(3 + a*8 + 4 + f)] = tf32c(c2);
                }
            #pragma unroll
            for (int d = 27; d < 32; d++) pr[pcol(d)] = 0u;
        } else {
            int t2 = tid - 128;
            int qq = t2 >> 5, e = (t2 & 31)*4;
            float4 v = *(const float4*)&g_A1b[(size_t)(q0+qq)*TOK + e];
            *(float4*)&sA1b[qq*TOK + e] = v;
        }
        __syncthreads();

        // ---- phase A: h1 = relu(pes@W1rel + F1[j] + A1b[i]) ----
        #pragma unroll 1
        for (int m = 0; m < 8; m++){
            const unsigned* pr0 = pes + (m*16 + g)*PESS;
            const unsigned* pr1 = pr0 + 8*PESS;
            uint4 lo0 = *(const uint4*)(pr0 + 4*tig);
            uint4 hi0 = *(const uint4*)(pr1 + 4*tig);
            uint4 lo1 = *(const uint4*)(pr0 + 16 + 4*tig);
            uint4 hi1 = *(const uint4*)(pr1 + 16 + 4*tig);
            int r0 = m*16 + g, r1 = r0 + 8, qq = m >> 1;
            int j0 = sj[qq*KN + (r0 & 31)];
            int j1 = sj[qq*KN + (r1 & 31)];
            float2 f1v[2][2], a1v[2];
            #pragma unroll
            for (int nt = 0; nt < 2; nt++){
                int c0 = n0 + nt*8 + 2*tig;
                f1v[nt][0] = *(const float2*)&f1b[(size_t)j0*TOK + c0];
                f1v[nt][1] = *(const float2*)&f1b[(size_t)j1*TOK + c0];
                a1v[nt]    = *(const float2*)&sA1b[qq*TOK + c0];
            }
            float acc[2][4] = {{0,0,0,0},{0,0,0,0}};
            #pragma unroll
            for (int nt = 0; nt < 2; nt++){
                mma8(acc[nt], lo0.x, hi0.x, lo0.z, hi0.z, bw1[0][nt][0], bw1[0][nt][1]);
                mma8(acc[nt], lo0.y, hi0.y, lo0.w, hi0.w, bw1[1][nt][0], bw1[1][nt][1]);
                mma8(acc[nt], lo1.x, hi1.x, lo1.z, hi1.z, bw1[2][nt][0], bw1[2][nt][1]);
                mma8(acc[nt], lo1.y, hi1.y, lo1.w, hi1.w, bw1[3][nt][0], bw1[3][nt][1]);
            }
            #pragma unroll
            for (int nt = 0; nt < 2; nt++){
                float v00 = fmaxf(acc[nt][0] + f1v[nt][0].x + a1v[nt].x, 0.f);
                float v01 = fmaxf(acc[nt][1] + f1v[nt][0].y + a1v[nt].y, 0.f);
                float v10 = fmaxf(acc[nt][2] + f1v[nt][1].x + a1v[nt].x, 0.f);
                float v11 = fmaxf(acc[nt][3] + f1v[nt][1].y + a1v[nt].y, 0.f);
                h1s[r0*H1S + pc[nt][0]] = tf32c(v00);
                h1s[r0*H1S + pc[nt][1]] = tf32c(v01);
                h1s[r1*H1S + pc[nt][0]] = tf32c(v10);
                h1s[r1*H1S + pc[nt][1]] = tf32c(v11);
            }
        }
        __syncthreads();

        // ---- phase B: h2 = h1 @ W2, then max over rows of each query ----
        #pragma unroll 1
        for (int m = 0; m < 8; m++){
            const unsigned* a0p = h1s + (m*16 + g)*H1S;
            const unsigned* a1p = a0p + 8*H1S;
            float acc[2][4] = {{0,0,0,0},{0,0,0,0}};
            #pragma unroll
            for (int kp = 0; kp < 8; kp++){
                uint4 lo = *(const uint4*)(a0p + kp*16 + 4*tig);
                uint4 hi = *(const uint4*)(a1p + kp*16 + 4*tig);
                #pragma unroll
                for (int nt = 0; nt < 2; nt++){
                    mma8(acc[nt], lo.x, hi.x, lo.z, hi.z,
                         bw2[2*kp  ][nt][0], bw2[2*kp  ][nt][1]);
                    mma8(acc[nt], lo.y, hi.y, lo.w, hi.w,
                         bw2[2*kp+1][nt][0], bw2[2*kp+1][nt][1]);
                }
            }
            #pragma unroll
            for (int nt = 0; nt < 2; nt++){
                float m0 = fmaxf(acc[nt][0], acc[nt][2]);  // col 2*tig
                float m1 = fmaxf(acc[nt][1], acc[nt][3]);  // col 2*tig+1
                #pragma unroll
                for (int off = 16; off >= 4; off >>= 1){
                    m0 = fmaxf(m0, __shfl_xor_sync(0xFFFFFFFFu, m0, off));
                    m1 = fmaxf(m1, __shfl_xor_sync(0xFFFFFFFFu, m1, off));
                }
                if (lane < 4){
                    int c0 = n0 + nt*8 + 2*tig;
                    atomicMax(&sbmax[b*TOK + c0    ], f2ord(m0));
                    atomicMax(&sbmax[b*TOK + c0 + 1], f2ord(m1));
                }
            }
        }
    }
    __syncthreads();
    atomicMax(&g_gmax[tid], sbmax[tid]);
}

// ---------------------------------------------------------------------------
// Final: g = max + b2 ; g = relu(g@W3+b3) ; out = g@W4+b4   (fp32)
// ---------------------------------------------------------------------------
__global__ void final_kernel(const float* __restrict__ b2,
                             const float* __restrict__ W3,
                             const float* __restrict__ b3,
                             const float* __restrict__ W4,
                             const float* __restrict__ b4,
                             float* __restrict__ out){
    int b = blockIdx.x, c = threadIdx.x;
    __shared__ float gbuf[TOK], hbuf[TOK];
    gbuf[c] = ord2f(g_gmax[b*TOK + c]) + b2[c];
    __syncthreads();
    float acc = b3[c];
    #pragma unroll 16
    for (int d = 0; d < TOK; d++) acc += gbuf[d] * W3[d*TOK + c];
    hbuf[c] = fmaxf(acc, 0.f);
    __syncthreads();
    float acc2 = b4[c];
    #pragma unroll 16
    for (int d = 0; d < TOK; d++) acc2 += hbuf[d] * W4[d*TOK + c];
    out[b*TOK + c] = acc2;
}

// ---------------------------------------------------------------------------
extern "C" void kernel_launch(void* const* d_in, const int* in_sizes, int n_in,
                              void* d_out, int out_size){
    const float* xyz  = (const float*)d_in[0];
    const float* feat = (const float*)d_in[1];
    const float* W1   = (const float*)d_in[2];
    const float* b1   = (const float*)d_in[3];
    const float* W2   = (const float*)d_in[4];
    const float* b2   = (const float*)d_in[5];
    const float* W3   = (const float*)d_in[6];
    const float* b3   = (const float*)d_in[7];
    const float* W4   = (const float*)d_in[8];
    const float* b4   = (const float*)d_in[9];
    float* out = (float*)d_out;

    const int MAIN_SMEM = (128*H1S + 128*PESS)*4 + 4*TOK*4 + 4*KN*4 + BN*TOK*4;
    cudaFuncSetAttribute(main_kernel,
                         cudaFuncAttributeMaxDynamicSharedMemorySize, MAIN_SMEM);

    precompute_kernel<<<CQ, 128>>>(xyz, feat, W1, b1);
    neighbor_kernel<<<CQ/8, 256>>>(xyz);
    main_kernel<<<148, 256, MAIN_SMEM>>>(xyz, W1, W2);
    final_kernel<<<BN, TOK>>>(b2, W3, b3, W4, b4, out);
}